// round 7
// baseline (speedup 1.0000x reference)
#include <cuda_runtime.h>
#include <math.h>

typedef unsigned long long ull;

#define TT   512
#define BBAT 64
#define DD   128
#define UU   256
#define G3   768
#define NBLK 128
#define TPB  256
#define CH   8
#define NGRP 4
#define GBLK 32

// ---------------- device scratch ----------------
__device__ float g_xg[(size_t)BBAT * TT * G3];   // x @ W_in + bias0
__device__ float g_basep[2][BBAT][CH][UU];       // chunk-base partials (2 j-halves)
// per-block arrival flags (monotonic across launches), 32B-strided
__device__ volatile unsigned g_flag[NBLK * 8];

// packed f32x2 helpers (Blackwell; ptxas never emits FFMA2 from C++)
#define FMA2(acc, a, b) \
    asm("fma.rn.f32x2 %0, %1, %2, %0;" : "+l"(acc) : "l"(a), "l"(b))
#define ADD2(acc, a) \
    asm("add.rn.f32x2 %0, %1, %0;" : "+l"(acc) : "l"(a))
__device__ __forceinline__ ull pack2(float x, float y) {
    ull r; asm("mov.b64 %0, {%1, %2};" : "=l"(r) : "f"(x), "f"(y)); return r;
}
__device__ __forceinline__ void unpack2(ull v, float& x, float& y) {
    asm("mov.b64 {%0, %1}, %2;" : "=f"(x), "=f"(y) : "l"(v));
}
__device__ __forceinline__ float tanh_fast(float v) {
    float y; asm("tanh.approx.f32 %0, %1;" : "=f"(y) : "f"(v)); return y;
}

// Flag-array group barrier (32 CTAs/group, all resident).
// Release: __syncthreads gives tid0 happens-before over all block stores;
// tid0 does ONE gpu fence then publishes its flag. 32 pollers (one per peer
// flag) spin in parallel, each does an acquire fence after observing.
// Replay-safe: targets are base-relative (flags persist across graph replays;
// all flags are uniform when a launch completes).
__device__ __forceinline__ void group_sync(int gid, int blk, unsigned target) {
    __syncthreads();
    if (threadIdx.x == 0) {
        __threadfence();
        g_flag[blk * 8] = target;
    }
    if (threadIdx.x < GBLK) {
        const int peer = (gid * GBLK + (int)threadIdx.x) * 8;
        while ((int)(g_flag[peer] - target) < 0) { }
        __threadfence();
    }
    __syncthreads();
}

// smem layout (float offsets)
#define WD_OFF   0        // Wk: 128 k2 x 24 c x 16B entries = 12288 f
#define AB_OFF   12288    // Ab: 8 bp x 256 k ull = 4096 f
#define BIG_OFF  16384    // 8192 f union: stage0 As / chunk Hs
#define CS_OFF   24576    // 256 f chunk cond tile
#define CSM_OFF  24832    // 256 f per-step cond stage (double-buffered)
#define GH_OFF   25088    // 384 f h-side preactivations
#define SMEM_F   25472    // 101888 B

__global__ void __launch_bounds__(TPB, 1) dag_rnn_kernel(
    const float* __restrict__ x,     // (B,T,D)
    const float* __restrict__ cond,  // (B,T,T)
    const float* __restrict__ Win,   // (D,3U)
    const float* __restrict__ Wrec,  // (U,3U)
    const float* __restrict__ bias,  // (2,3U)
    float* __restrict__ out)         // (B,T,U) == H storage
{
    extern __shared__ __align__(16) float smem[];
    ull*   Wk  = (ull*)(smem + WD_OFF);   // entry (k2,c): 2 ull {w,w} for k=2k2,2k2+1
    ull*   Ab  = (ull*)(smem + AB_OFF);   // [bp][k] = {A[2bp,k], A[2bp+1,k]}
    float* BIG = smem + BIG_OFF;
    float* Cs  = smem + CS_OFF;
    float* Csm = smem + CSM_OFF;
    float* Gh  = smem + GH_OFF;

    const int tid = threadIdx.x;
    const int blk = blockIdx.x;
    const int gid = blk >> 5;

    const unsigned base = g_flag[blk * 8];   // uniform across grid at launch start
    unsigned gen = 0;

    const int b0 = (blk >> 5) * 16;    // batch tile
    const int u0 = (blk & 31) * 8;     // u tile

    // hg-GEMM identity (tid<192): 8 batch-pairs x 24 cols
    const int c  = tid % 24;
    const int bp = tid / 24;
    const int gcol = (c >> 3) * UU + u0 + (c & 7);
    float bh = 0.f;
    if (tid < 192) bh = bias[G3 + gcol];

    // ---- preload Wrec slice: Wk entry (k>>1, c), parity (k&1) = {w,w} ----
    for (int idx = tid; idx < 24 * UU; idx += TPB) {
        int cc = idx >> 8, k = idx & 255;
        int colc = (cc >> 3) * UU + u0 + (cc & 7);
        float w = Wrec[(size_t)k * G3 + colc];
        Wk[((k >> 1) * 24 + cc) * 2 + (k & 1)] = pack2(w, w);
    }

    // ================= stage 0: g_xg = x @ Win + bias0 =================
    {
        float* As = BIG;                       // 32 x 128
        const float bz  = bias[tid];
        const float br  = bias[UU + tid];
        const float bhh = bias[2 * UU + tid];
        const int row0 = blk * 256;
        for (int rt = 0; rt < 8; ++rt) {
            const int rbase = row0 + rt * 32;
            __syncthreads();
            for (int idx = tid; idx < 32 * DD; idx += TPB)
                As[idx] = x[(size_t)rbase * DD + idx];
            __syncthreads();
            for (int rs = 0; rs < 4; ++rs) {
                float a0[8], a1[8], a2[8];
                #pragma unroll
                for (int r = 0; r < 8; ++r) { a0[r] = 0.f; a1[r] = 0.f; a2[r] = 0.f; }
                const float* asr = As + (rs * 8) * DD;
                #pragma unroll 4
                for (int k = 0; k < DD; ++k) {
                    float w0 = __ldg(&Win[(size_t)k * G3 + tid]);
                    float w1 = __ldg(&Win[(size_t)k * G3 + UU + tid]);
                    float w2 = __ldg(&Win[(size_t)k * G3 + 2 * UU + tid]);
                    #pragma unroll
                    for (int r = 0; r < 8; ++r) {
                        float a = asr[r * DD + k];
                        a0[r] += a * w0; a1[r] += a * w1; a2[r] += a * w2;
                    }
                }
                #pragma unroll
                for (int r = 0; r < 8; ++r) {
                    size_t ro = (size_t)(rbase + rs * 8 + r) * G3;
                    g_xg[ro + tid]          = a0[r] + bz;
                    g_xg[ro + UU + tid]     = a1[r] + br;
                    g_xg[ro + 2 * UU + tid] = a2[r] + bhh;
                }
            }
        }
    }
    group_sync(gid, blk, base + (++gen));

    const float invT = 1.0f / (float)TT;

    // gate-input registers, prefetched one step ahead
    float xz = 0.f, xr = 0.f, xh = 0.f;
    if (tid < 128) {
        const int uq = tid & 7, bb2 = tid >> 3;
        const size_t xo = ((size_t)(b0 + bb2) * TT + 0) * G3 + u0 + uq;
        xz = __ldg(&g_xg[xo]);
        xr = __ldg(&g_xg[xo + UU]);
        xh = __ldg(&g_xg[xo + 2 * UU]);
    }

    // phase-A identity (all 256 threads): u-pair x bb-half
    const int u2  = tid & 127;
    const int bbh = tid >> 7;

    float2 pacc[8];          // correction prefetch for next step
    #pragma unroll
    for (int r = 0; r < 8; ++r) pacc[r] = make_float2(0.f, 0.f);

    for (int c0 = 0; c0 < TT; c0 += CH) {
        // ---------- chunk-base GEMM: 16 group batches x 2 j-halves ----------
        if (c0 > 0) {
            float* Hs = BIG;
            const int cb   = blk >> 1;
            const int jh   = blk & 1;
            const int kb   = c0 >> 1;
            const int jbeg = jh * kb;
            const float* hrow = out  + ((size_t)cb * TT + jbeg) * UU;
            const float* crow = cond + ((size_t)cb * TT + c0) * TT + jbeg;

            float acc[2][8];
            #pragma unroll
            for (int a = 0; a < 2; ++a)
                #pragma unroll
                for (int q = 0; q < 8; ++q) acc[a][q] = 0.f;

            const int lg = tid >> 5;
            const int ug = tid & 31;

            for (int jt = 0; jt < kb; jt += 32) {
                const int jn = (kb - jt < 32) ? (kb - jt) : 32;
                __syncthreads();
                for (int idx = tid; idx < jn * UU; idx += TPB)
                    Hs[idx] = __ldcg(&hrow[(size_t)jt * UU + idx]);
                {
                    int l = tid >> 5, jj = tid & 31;
                    if (jj < jn)
                        Cs[jj * CH + l] = __ldg(&crow[(size_t)l * TT + jt + jj]);
                }
                __syncthreads();
                if (tid < 128) {
                    for (int jj = 0; jj < jn; ++jj) {
                        float cv0 = Cs[jj * CH + lg];
                        float cv1 = Cs[jj * CH + lg + 4];
                        const float4* h4 = (const float4*)&Hs[jj * UU + ug * 8];
                        float4 ha = h4[0], hb2 = h4[1];
                        acc[0][0] += cv0 * ha.x;  acc[0][1] += cv0 * ha.y;
                        acc[0][2] += cv0 * ha.z;  acc[0][3] += cv0 * ha.w;
                        acc[0][4] += cv0 * hb2.x; acc[0][5] += cv0 * hb2.y;
                        acc[0][6] += cv0 * hb2.z; acc[0][7] += cv0 * hb2.w;
                        acc[1][0] += cv1 * ha.x;  acc[1][1] += cv1 * ha.y;
                        acc[1][2] += cv1 * ha.z;  acc[1][3] += cv1 * ha.w;
                        acc[1][4] += cv1 * hb2.x; acc[1][5] += cv1 * hb2.y;
                        acc[1][6] += cv1 * hb2.z; acc[1][7] += cv1 * hb2.w;
                    }
                }
            }
            if (tid < 128) {
                #pragma unroll
                for (int li = 0; li < 2; ++li) {
                    const int l = lg + li * 4;
                    float* dst = &g_basep[jh][cb][l][ug * 8];
                    ((float4*)dst)[0] = make_float4(acc[li][0], acc[li][1],
                                                    acc[li][2], acc[li][3]);
                    ((float4*)dst)[1] = make_float4(acc[li][4], acc[li][5],
                                                    acc[li][6], acc[li][7]);
                }
            }
            group_sync(gid, blk, base + (++gen));
        }

        // ---------------- sequential steps within chunk ----------------
        for (int l = 0; l < CH; ++l) {
            const int i = c0 + l;
            const int lnext = (l < CH - 1) ? (l + 1) : 0;
            float* CsmCur = Csm + (l & 1) * 128;
            float* CsmNxt = Csm + ((l + 1) & 1) * 128;

            // ---- phase A: finish next_state, write Ab ----
            {
                float2 acc[8];
                if (l == 0) {
                    if (c0 > 0) {
                        #pragma unroll
                        for (int r = 0; r < 8; ++r) {
                            const int bb = bbh * 8 + r;
                            float2 p0 = __ldcg((const float2*)&g_basep[0][b0 + bb][0][2 * u2]);
                            float2 p1 = __ldcg((const float2*)&g_basep[1][b0 + bb][0][2 * u2]);
                            acc[r].x = p0.x + p1.x;
                            acc[r].y = p0.y + p1.y;
                        }
                    } else {
                        #pragma unroll
                        for (int r = 0; r < 8; ++r) acc[r] = make_float2(0.f, 0.f);
                    }
                } else {
                    // prefetched sum covers jj < l-1; add newest row jj = l-1
                    const int jj = l - 1;
                    #pragma unroll
                    for (int r = 0; r < 8; ++r) {
                        const int bb = bbh * 8 + r;
                        float cv = CsmCur[jj * 16 + bb];
                        float2 h = __ldcg((const float2*)
                            &out[((size_t)(b0 + bb) * TT + c0 + jj) * UU + 2 * u2]);
                        acc[r].x = pacc[r].x + cv * h.x;
                        acc[r].y = pacc[r].y + cv * h.y;
                    }
                }
                // write packed batch-pair entries (STS.128, conflict-free)
                #pragma unroll
                for (int p = 0; p < 4; ++p) {
                    const int bpw = bbh * 4 + p;
                    ulonglong2 e;
                    e.x = pack2(acc[2 * p].x * invT, acc[2 * p + 1].x * invT);
                    e.y = pack2(acc[2 * p].y * invT, acc[2 * p + 1].y * invT);
                    *(ulonglong2*)(Ab + bpw * 256 + 2 * u2) = e;
                }
            }
            __syncthreads();

            // ---- prefetch next step's cond + gate inputs ----
            float cnext = 0.f, xzp = 0.f, xrp = 0.f, xhp = 0.f;
            if (tid < 128) {
                const int jj = tid >> 4, bb = tid & 15;
                if (jj < lnext)
                    cnext = __ldg(&cond[((size_t)(b0 + bb) * TT + (i + 1)) * TT
                                        + c0 + jj]);
                if (i + 1 < TT) {
                    const int uq = tid & 7, bb2 = tid >> 3;
                    const size_t xo = ((size_t)(b0 + bb2) * TT + (i + 1)) * G3 + u0 + uq;
                    xzp = __ldg(&g_xg[xo]);
                    xrp = __ldg(&g_xg[xo + UU]);
                    xhp = __ldg(&g_xg[xo + 2 * UU]);
                }
            }

            // ---- hg = next @ Wrec via packed FFMA2 (192 threads) ----
            if (tid < 192) {
                const ulonglong2* wk = ((const ulonglong2*)Wk) + c;   // entry (k2,c)
                const ulonglong2* ab = ((const ulonglong2*)Ab) + bp * 128;
                ull acc0 = 0ull, acc1 = 0ull, acc2 = 0ull, acc3 = 0ull;
                #pragma unroll 8
                for (int k2 = 0; k2 < 128; k2 += 2) {
                    ulonglong2 w0 = wk[(size_t)k2 * 24];
                    ulonglong2 a0 = ab[k2];
                    ulonglong2 w1 = wk[(size_t)(k2 + 1) * 24];
                    ulonglong2 a1 = ab[k2 + 1];
                    FMA2(acc0, a0.x, w0.x);
                    FMA2(acc1, a0.y, w0.y);
                    FMA2(acc2, a1.x, w1.x);
                    FMA2(acc3, a1.y, w1.y);
                }
                ADD2(acc0, acc1);
                ADD2(acc2, acc3);
                ADD2(acc0, acc2);
                float g0, g1;
                unpack2(acc0, g0, g1);
                Gh[(2 * bp)     * 24 + c] = g0 + bh;
                Gh[(2 * bp + 1) * 24 + c] = g1 + bh;
            }
            __syncthreads();

            // ---- gates + output; stage next cond ----
            if (tid < 128) {
                const int uq = tid & 7, bb = tid >> 3;
                float hz = Gh[bb * 24 + uq];
                float hr = Gh[bb * 24 + 8 + uq];
                float hh = Gh[bb * 24 + 16 + uq];
                float z  = 1.0f / (1.0f + __expf(-(xz + hz)));
                float r  = 1.0f / (1.0f + __expf(-(xr + hr)));
                float hc = tanh_fast(xh + r * hh);
                float h  = ((const float*)Ab)[((bb >> 1) * 256 + u0 + uq) * 2 + (bb & 1)];
                out[((size_t)(b0 + bb) * TT + i) * UU + u0 + uq]
                    = z * h + (1.0f - z) * hc;
                if ((tid >> 4) < lnext) CsmNxt[tid] = cnext;
            }
            xz = xzp; xr = xrp; xh = xhp;
            __syncthreads();   // CsmNxt visible for pacc prefetch

            // ---- pacc prefetch for next step (rows <= c0+l-1 are visible) ----
            if (lnext > 0) {
                #pragma unroll
                for (int r = 0; r < 8; ++r) pacc[r] = make_float2(0.f, 0.f);
                if (c0 > 0) {
                    #pragma unroll
                    for (int r = 0; r < 8; ++r) {
                        const int bb = bbh * 8 + r;
                        float2 p0 = __ldcg((const float2*)&g_basep[0][b0 + bb][lnext][2 * u2]);
                        float2 p1 = __ldcg((const float2*)&g_basep[1][b0 + bb][lnext][2 * u2]);
                        pacc[r].x = p0.x + p1.x;
                        pacc[r].y = p0.y + p1.y;
                    }
                }
                for (int jj = 0; jj < lnext - 1; ++jj) {
                    #pragma unroll
                    for (int r = 0; r < 8; ++r) {
                        const int bb = bbh * 8 + r;
                        float cv = CsmNxt[jj * 16 + bb];
                        float2 h = __ldcg((const float2*)
                            &out[((size_t)(b0 + bb) * TT + c0 + jj) * UU + 2 * u2]);
                        pacc[r].x += cv * h.x;
                        pacc[r].y += cv * h.y;
                    }
                }
            }
            group_sync(gid, blk, base + (++gen));
        }
    }
}

extern "C" void kernel_launch(void* const* d_in, const int* in_sizes, int n_in,
                              void* d_out, int out_size) {
    const float* x    = (const float*)d_in[0];
    const float* cond = (const float*)d_in[1];
    const float* Win  = (const float*)d_in[2];
    const float* Wrec = (const float*)d_in[3];
    const float* bias = (const float*)d_in[4];
    float* out = (float*)d_out;

    const int smem_bytes = SMEM_F * sizeof(float);
    static bool attr_set = false;
    if (!attr_set) {
        cudaFuncSetAttribute(dag_rnn_kernel,
                             cudaFuncAttributeMaxDynamicSharedMemorySize, smem_bytes);
        attr_set = true;
    }
    dag_rnn_kernel<<<NBLK, TPB, smem_bytes>>>(x, cond, Win, Wrec, bias, out);
}

// round 9
// speedup vs baseline: 1.0514x; 1.0514x over previous
#include <cuda_runtime.h>
#include <math.h>

typedef unsigned long long ull;

#define TT   512
#define BBAT 64
#define DD   128
#define UU   256
#define G3   768
#define NBLK 128
#define TPB  256
#define CH   8
#define NGRP 4
#define GBLK 32

// ---------------- device scratch ----------------
__device__ float g_xg[(size_t)BBAT * TT * G3];   // x @ W_in + bias0
__device__ float g_basep[2][BBAT][CH][UU];       // chunk-base partials (2 j-halves)
// per-group barrier state, 256B-strided
__device__ unsigned g_barcnt[NGRP * 64];
__device__ volatile unsigned g_bargen[NGRP * 64];

// packed f32x2 helpers (Blackwell; ptxas never emits FFMA2 from C++)
#define FMA2(acc, a, b) \
    asm("fma.rn.f32x2 %0, %1, %2, %0;" : "+l"(acc) : "l"(a), "l"(b))
#define ADD2(acc, a) \
    asm("add.rn.f32x2 %0, %1, %0;" : "+l"(acc) : "l"(a))
__device__ __forceinline__ ull pack2(float x, float y) {
    ull r; asm("mov.b64 %0, {%1, %2};" : "=l"(r) : "f"(x), "f"(y)); return r;
}
__device__ __forceinline__ void unpack2(ull v, float& x, float& y) {
    asm("mov.b64 {%0, %1}, %2;" : "=f"(x), "=f"(y) : "l"(v));
}
__device__ __forceinline__ float tanh_fast(float v) {
    float y; asm("tanh.approx.f32 %0, %1;" : "=f"(y) : "f"(v)); return y;
}

// Group barrier (R6-proven): 32 CTAs/group, all resident. Per-thread
// __threadfence (gpu-scope release) before arrival; single-leader
// nanosleep spin; fence on wake. Cross-block data read via __ldcg.
__device__ __forceinline__ void group_sync(int gid) {
    __threadfence();
    __syncthreads();
    if (threadIdx.x == 0) {
        const int s = gid * 64;
        unsigned g = g_bargen[s];
        if (atomicAdd(&g_barcnt[s], 1u) == GBLK - 1) {
            atomicExch(&g_barcnt[s], 0u);
            __threadfence();
            g_bargen[s] = g + 1;
        } else {
            while (g_bargen[s] == g) { __nanosleep(32); }
        }
        __threadfence();
    }
    __syncthreads();
}

// smem layout (float offsets)
#define WK_OFF   0        // Wk: 128 k2 x 24 c x 16B entries = 12288 f
#define AB_OFF   12288    // Ab: 8 bp x 256 k ull = 4096 f
#define BIG_OFF  16384    // 8192 f union: stage0 As / chunk Hs
#define CS_OFF   24576    // 256 f chunk cond tile
#define CSM_OFF  24832    // 256 f per-step cond stage (double-buffered)
#define GH_OFF   25088    // 384 f h-side preactivations
#define SMEM_F   25472    // 101888 B

__global__ void __launch_bounds__(TPB, 1) dag_rnn_kernel(
    const float* __restrict__ x,     // (B,T,D)
    const float* __restrict__ cond,  // (B,T,T)
    const float* __restrict__ Win,   // (D,3U)
    const float* __restrict__ Wrec,  // (U,3U)
    const float* __restrict__ bias,  // (2,3U)
    float* __restrict__ out)         // (B,T,U) == H storage
{
    extern __shared__ __align__(16) float smem[];
    ull*   Wk  = (ull*)(smem + WK_OFF);   // entry (k2,c): {w2k,w2k}{w2k+1,w2k+1}
    ull*   Ab  = (ull*)(smem + AB_OFF);   // [bp][k] = {A[2bp,k], A[2bp+1,k]}
    float* BIG = smem + BIG_OFF;
    float* Cs  = smem + CS_OFF;
    float* Csm = smem + CSM_OFF;          // 2 x 128
    float* Gh  = smem + GH_OFF;

    const int tid = threadIdx.x;
    const int blk = blockIdx.x;
    const int gid = blk >> 5;

    const int b0 = (blk >> 5) * 16;    // batch tile
    const int u0 = (blk & 31) * 8;     // u tile

    // hg-GEMM identity (tid<192): 8 batch-pairs x 24 cols
    const int c  = tid % 24;
    const int bp = tid / 24;
    const int gcol = (c >> 3) * UU + u0 + (c & 7);
    float bh = 0.f;
    if (tid < 192) bh = bias[G3 + gcol];

    // ---- preload Wrec slice: entry (k>>1, c), slot (k&1) = {w,w} ----
    for (int idx = tid; idx < 24 * UU; idx += TPB) {
        int cc = idx >> 8, k = idx & 255;
        int colc = (cc >> 3) * UU + u0 + (cc & 7);
        float w = Wrec[(size_t)k * G3 + colc];
        Wk[((k >> 1) * 24 + cc) * 2 + (k & 1)] = pack2(w, w);
    }

    // ================= stage 0: g_xg = x @ Win + bias0 =================
    {
        float* As = BIG;                       // 32 x 128
        const float bz  = bias[tid];
        const float br  = bias[UU + tid];
        const float bhh = bias[2 * UU + tid];
        const int row0 = blk * 256;
        for (int rt = 0; rt < 8; ++rt) {
            const int rbase = row0 + rt * 32;
            __syncthreads();
            for (int idx = tid; idx < 32 * DD; idx += TPB)
                As[idx] = x[(size_t)rbase * DD + idx];
            __syncthreads();
            for (int rs = 0; rs < 4; ++rs) {
                float a0[8], a1[8], a2[8];
                #pragma unroll
                for (int r = 0; r < 8; ++r) { a0[r] = 0.f; a1[r] = 0.f; a2[r] = 0.f; }
                const float* asr = As + (rs * 8) * DD;
                #pragma unroll 4
                for (int k = 0; k < DD; ++k) {
                    float w0 = __ldg(&Win[(size_t)k * G3 + tid]);
                    float w1 = __ldg(&Win[(size_t)k * G3 + UU + tid]);
                    float w2 = __ldg(&Win[(size_t)k * G3 + 2 * UU + tid]);
                    #pragma unroll
                    for (int r = 0; r < 8; ++r) {
                        float a = asr[r * DD + k];
                        a0[r] += a * w0; a1[r] += a * w1; a2[r] += a * w2;
                    }
                }
                #pragma unroll
                for (int r = 0; r < 8; ++r) {
                    size_t ro = (size_t)(rbase + rs * 8 + r) * G3;
                    g_xg[ro + tid]          = a0[r] + bz;
                    g_xg[ro + UU + tid]     = a1[r] + br;
                    g_xg[ro + 2 * UU + tid] = a2[r] + bhh;
                }
            }
        }
    }
    group_sync(gid);

    const float invT = 1.0f / (float)TT;

    // gate-input registers, prefetched one step ahead
    float xz = 0.f, xr = 0.f, xh = 0.f;
    if (tid < 128) {
        const int uq = tid & 7, bb2 = tid >> 3;
        const size_t xo = ((size_t)(b0 + bb2) * TT + 0) * G3 + u0 + uq;
        xz = __ldg(&g_xg[xo]);
        xr = __ldg(&g_xg[xo + UU]);
        xh = __ldg(&g_xg[xo + 2 * UU]);
    }

    for (int c0 = 0; c0 < TT; c0 += CH) {
        // ---------- chunk-base GEMM: 16 group batches x 2 j-halves ----------
        if (c0 > 0) {
            float* Hs = BIG;
            const int cb   = blk >> 1;
            const int jh   = blk & 1;
            const int kb   = c0 >> 1;
            const int jbeg = jh * kb;
            const float* hrow = out  + ((size_t)cb * TT + jbeg) * UU;
            const float* crow = cond + ((size_t)cb * TT + c0) * TT + jbeg;

            float acc[2][8];
            #pragma unroll
            for (int a = 0; a < 2; ++a)
                #pragma unroll
                for (int q = 0; q < 8; ++q) acc[a][q] = 0.f;

            const int lg = tid >> 5;
            const int ug = tid & 31;

            for (int jt = 0; jt < kb; jt += 32) {
                const int jn = (kb - jt < 32) ? (kb - jt) : 32;
                __syncthreads();
                for (int idx = tid; idx < jn * UU; idx += TPB)
                    Hs[idx] = __ldcg(&hrow[(size_t)jt * UU + idx]);
                {
                    int l = tid >> 5, jj = tid & 31;
                    if (jj < jn)
                        Cs[jj * CH + l] = __ldg(&crow[(size_t)l * TT + jt + jj]);
                }
                __syncthreads();
                if (tid < 128) {
                    for (int jj = 0; jj < jn; ++jj) {
                        float cv0 = Cs[jj * CH + lg];
                        float cv1 = Cs[jj * CH + lg + 4];
                        const float4* h4 = (const float4*)&Hs[jj * UU + ug * 8];
                        float4 ha = h4[0], hb2 = h4[1];
                        acc[0][0] += cv0 * ha.x;  acc[0][1] += cv0 * ha.y;
                        acc[0][2] += cv0 * ha.z;  acc[0][3] += cv0 * ha.w;
                        acc[0][4] += cv0 * hb2.x; acc[0][5] += cv0 * hb2.y;
                        acc[0][6] += cv0 * hb2.z; acc[0][7] += cv0 * hb2.w;
                        acc[1][0] += cv1 * ha.x;  acc[1][1] += cv1 * ha.y;
                        acc[1][2] += cv1 * ha.z;  acc[1][3] += cv1 * ha.w;
                        acc[1][4] += cv1 * hb2.x; acc[1][5] += cv1 * hb2.y;
                        acc[1][6] += cv1 * hb2.z; acc[1][7] += cv1 * hb2.w;
                    }
                }
            }
            if (tid < 128) {
                #pragma unroll
                for (int li = 0; li < 2; ++li) {
                    const int l = lg + li * 4;
                    float* dst = &g_basep[jh][cb][l][ug * 8];
                    ((float4*)dst)[0] = make_float4(acc[li][0], acc[li][1],
                                                    acc[li][2], acc[li][3]);
                    ((float4*)dst)[1] = make_float4(acc[li][4], acc[li][5],
                                                    acc[li][6], acc[li][7]);
                }
            }
            group_sync(gid);
        }

        // ---------------- sequential steps within chunk ----------------
        for (int l = 0; l < CH; ++l) {
            const int i = c0 + l;
            const int lnext = (l < CH - 1) ? (l + 1) : 0;
            float* CsmCur = Csm + (l & 1) * 128;
            float* CsmNxt = Csm + ((l + 1) & 1) * 128;

            // ---- phase A: correction + base -> Ab (128 u-pairs x 2 bb-halves) ----
            {
                const int u2  = tid & 127;
                const int bbh = tid >> 7;
                float2 acc[8];
                if (c0 > 0) {
                    #pragma unroll
                    for (int r = 0; r < 8; ++r) {
                        const int bb = bbh * 8 + r;
                        float2 p0 = __ldcg((const float2*)&g_basep[0][b0 + bb][l][2 * u2]);
                        float2 p1 = __ldcg((const float2*)&g_basep[1][b0 + bb][l][2 * u2]);
                        acc[r].x = p0.x + p1.x;
                        acc[r].y = p0.y + p1.y;
                    }
                } else {
                    #pragma unroll
                    for (int r = 0; r < 8; ++r) acc[r] = make_float2(0.f, 0.f);
                }
                for (int jj = 0; jj < l; ++jj) {
                    #pragma unroll
                    for (int r = 0; r < 8; ++r) {
                        const int bb = bbh * 8 + r;
                        float cv = CsmCur[jj * 16 + bb];
                        float2 h = __ldcg((const float2*)
                            &out[((size_t)(b0 + bb) * TT + c0 + jj) * UU + 2 * u2]);
                        acc[r].x += cv * h.x;
                        acc[r].y += cv * h.y;
                    }
                }
                // packed batch-pair writes: 4 x STS.128, conflict-free
                #pragma unroll
                for (int p = 0; p < 4; ++p) {
                    const int bpw = bbh * 4 + p;
                    ulonglong2 e;
                    e.x = pack2(acc[2 * p].x * invT, acc[2 * p + 1].x * invT);
                    e.y = pack2(acc[2 * p].y * invT, acc[2 * p + 1].y * invT);
                    *(ulonglong2*)(Ab + bpw * 256 + 2 * u2) = e;
                }
            }
            __syncthreads();

            // ---- prefetch next step's cond + gate inputs ----
            float cnext = 0.f, xzp = 0.f, xrp = 0.f, xhp = 0.f;
            if (tid < 128) {
                const int jj = tid >> 4, bb = tid & 15;
                if (jj < lnext)
                    cnext = __ldg(&cond[((size_t)(b0 + bb) * TT + (i + 1)) * TT
                                        + c0 + jj]);
                if (i + 1 < TT) {
                    const int uq = tid & 7, bb2 = tid >> 3;
                    const size_t xo = ((size_t)(b0 + bb2) * TT + (i + 1)) * G3 + u0 + uq;
                    xzp = __ldg(&g_xg[xo]);
                    xrp = __ldg(&g_xg[xo + UU]);
                    xhp = __ldg(&g_xg[xo + 2 * UU]);
                }
            }

            // ---- hg = next @ Wrec via packed FFMA2 (192 threads) ----
            if (tid < 192) {
                const ulonglong2* wk = ((const ulonglong2*)Wk) + c;   // entry (k2,c)
                const ulonglong2* ab = ((const ulonglong2*)Ab) + bp * 128;
                ull acc0 = 0ull, acc1 = 0ull, acc2 = 0ull, acc3 = 0ull;
                #pragma unroll 8
                for (int k2 = 0; k2 < 128; k2 += 2) {
                    ulonglong2 w0 = wk[(size_t)k2 * 24];
                    ulonglong2 a0 = ab[k2];
                    ulonglong2 w1 = wk[(size_t)(k2 + 1) * 24];
                    ulonglong2 a1 = ab[k2 + 1];
                    FMA2(acc0, a0.x, w0.x);
                    FMA2(acc1, a0.y, w0.y);
                    FMA2(acc2, a1.x, w1.x);
                    FMA2(acc3, a1.y, w1.y);
                }
                ADD2(acc0, acc1);
                ADD2(acc2, acc3);
                ADD2(acc0, acc2);
                float g0, g1;
                unpack2(acc0, g0, g1);
                Gh[(2 * bp)     * 24 + c] = g0 + bh;
                Gh[(2 * bp + 1) * 24 + c] = g1 + bh;
            }
            __syncthreads();

            // ---- gates + output; stage next cond ----
            if (tid < 128) {
                const int uq = tid & 7, bb = tid >> 3;
                float hz = Gh[bb * 24 + uq];
                float hr = Gh[bb * 24 + 8 + uq];
                float hh = Gh[bb * 24 + 16 + uq];
                float z  = 1.0f / (1.0f + __expf(-(xz + hz)));
                float r  = 1.0f / (1.0f + __expf(-(xr + hr)));
                float hc = tanh_fast(xh + r * hh);
                float h  = ((const float*)Ab)[((bb >> 1) * 256 + u0 + uq) * 2 + (bb & 1)];
                out[((size_t)(b0 + bb) * TT + i) * UU + u0 + uq]
                    = z * h + (1.0f - z) * hc;
                if ((tid >> 4) < lnext) CsmNxt[tid] = cnext;
            }
            xz = xzp; xr = xrp; xh = xhp;
            group_sync(gid);
        }
    }
}

extern "C" void kernel_launch(void* const* d_in, const int* in_sizes, int n_in,
                              void* d_out, int out_size) {
    const float* x    = (const float*)d_in[0];
    const float* cond = (const float*)d_in[1];
    const float* Win  = (const float*)d_in[2];
    const float* Wrec = (const float*)d_in[3];
    const float* bias = (const float*)d_in[4];
    float* out = (float*)d_out;

    const int smem_bytes = SMEM_F * sizeof(float);
    static bool attr_set = false;
    if (!attr_set) {
        cudaFuncSetAttribute(dag_rnn_kernel,
                             cudaFuncAttributeMaxDynamicSharedMemorySize, smem_bytes);
        attr_set = true;
    }
    dag_rnn_kernel<<<NBLK, TPB, smem_bytes>>>(x, cond, Win, Wrec, bias, out);
}

// round 12
// speedup vs baseline: 1.0825x; 1.0296x over previous
#include <cuda_runtime.h>
#include <math.h>

typedef unsigned long long ull;

#define TT   512
#define BBAT 64
#define DD   128
#define UU   256
#define G3   768
#define NBLK 128
#define TPB  256
#define CH   8
#define NGRP 4
#define GBLK 32
#define SAB  129          // Ab row stride in ulonglong2 (2064B = 16 mod 128: conflict-free)

// ---------------- device scratch ----------------
__device__ float g_xg[(size_t)BBAT * TT * G3];   // x @ W_in + bias0
__device__ float g_basep[2][BBAT][CH][UU];       // chunk-base partials (2 j-halves)
// per-group barrier state, 256B-strided
__device__ unsigned g_barcnt[NGRP * 64];
__device__ volatile unsigned g_bargen[NGRP * 64];

// packed f32x2 helpers (Blackwell; ptxas never emits FFMA2 from C++)
#define FMA2(acc, a, b) \
    asm("fma.rn.f32x2 %0, %1, %2, %0;" : "+l"(acc) : "l"(a), "l"(b))
#define ADD2(acc, a) \
    asm("add.rn.f32x2 %0, %1, %0;" : "+l"(acc) : "l"(a))
__device__ __forceinline__ ull pack2(float x, float y) {
    ull r; asm("mov.b64 %0, {%1, %2};" : "=l"(r) : "f"(x), "f"(y)); return r;
}
__device__ __forceinline__ void unpack2(ull v, float& x, float& y) {
    asm("mov.b64 {%0, %1}, %2;" : "=f"(x), "=f"(y) : "l"(v));
}
__device__ __forceinline__ float tanh_fast(float v) {
    float y; asm("tanh.approx.f32 %0, %1;" : "=f"(y) : "f"(v)); return y;
}

// Group barrier (R6/R9-proven): 32 CTAs/group, all resident. Per-thread
// __threadfence (gpu-scope release) before arrival; central atomic count;
// single-leader nanosleep spin; fence on wake. Cross-block data via __ldcg.
__device__ __forceinline__ void group_sync(int gid) {
    __threadfence();
    __syncthreads();
    if (threadIdx.x == 0) {
        const int s = gid * 64;
        unsigned g = g_bargen[s];
        if (atomicAdd(&g_barcnt[s], 1u) == GBLK - 1) {
            atomicExch(&g_barcnt[s], 0u);
            __threadfence();
            g_bargen[s] = g + 1;
        } else {
            while (g_bargen[s] == g) { __nanosleep(32); }
        }
        __threadfence();
    }
    __syncthreads();
}

// smem layout (float offsets)
#define WK_OFF   0        // Wk: 128 k2 x 24 c x 16B entries = 12288 f
#define AB_OFF   12288    // Ab: 8 bp x 129 ull2 = 4128 f
#define BIG_OFF  16416    // 8192 f union: stage0 As / chunk Hs
#define CS_OFF   24608    // 256 f chunk cond tile
#define CSM_OFF  24864    // 256 f per-step cond stage (double-buffered)
#define GH_OFF   25120    // 384 f h-side preactivations
#define SMEM_F   25504    // 102016 B

__global__ void __launch_bounds__(TPB, 1) dag_rnn_kernel(
    const float* __restrict__ x,     // (B,T,D)
    const float* __restrict__ cond,  // (B,T,T)
    const float* __restrict__ Win,   // (D,3U)
    const float* __restrict__ Wrec,  // (U,3U)
    const float* __restrict__ bias,  // (2,3U)
    float* __restrict__ out)         // (B,T,U) == H storage
{
    extern __shared__ __align__(16) float smem[];
    ull*   Wk  = (ull*)(smem + WK_OFF);   // entry (k2,c): {w2k,w2k}{w2k+1,w2k+1}
    ull*   Ab  = (ull*)(smem + AB_OFF);   // row bp (stride SAB ull2): entry k2
    float* BIG = smem + BIG_OFF;
    float* Cs  = smem + CS_OFF;
    float* Csm = smem + CSM_OFF;          // 2 x 128
    float* Gh  = smem + GH_OFF;

    const int tid = threadIdx.x;
    const int blk = blockIdx.x;
    const int gid = blk >> 5;

    const int b0 = (blk >> 5) * 16;    // batch tile
    const int u0 = (blk & 31) * 8;     // u tile

    // hg-GEMM identity (tid<192), COLUMN-GROUPED warps:
    // warp w (0..5) covers cols 4w..4w+3; lane = 8 bp x 4 c
    const int c  = (tid >> 5) * 4 + ((tid & 31) >> 3);
    const int bp = tid & 7;
    const int gcol = (c >> 3) * UU + u0 + (c & 7);
    float bh = 0.f;
    if (tid < 192) bh = bias[G3 + gcol];

    // ---- preload Wrec slice: entry (k>>1, c), slot (k&1) = {w,w} ----
    for (int idx = tid; idx < 24 * UU; idx += TPB) {
        int cc = idx >> 8, k = idx & 255;
        int colc = (cc >> 3) * UU + u0 + (cc & 7);
        float w = Wrec[(size_t)k * G3 + colc];
        Wk[((k >> 1) * 24 + cc) * 2 + (k & 1)] = pack2(w, w);
    }

    // ================= stage 0: g_xg = x @ Win + bias0 =================
    {
        float* As = BIG;                       // 32 x 128
        const float bz  = bias[tid];
        const float br  = bias[UU + tid];
        const float bhh = bias[2 * UU + tid];
        const int row0 = blk * 256;
        for (int rt = 0; rt < 8; ++rt) {
            const int rbase = row0 + rt * 32;
            __syncthreads();
            for (int idx = tid; idx < 32 * DD; idx += TPB)
                As[idx] = x[(size_t)rbase * DD + idx];
            __syncthreads();
            for (int rs = 0; rs < 4; ++rs) {
                float a0[8], a1[8], a2[8];
                #pragma unroll
                for (int r = 0; r < 8; ++r) { a0[r] = 0.f; a1[r] = 0.f; a2[r] = 0.f; }
                const float* asr = As + (rs * 8) * DD;
                #pragma unroll 4
                for (int k = 0; k < DD; ++k) {
                    float w0 = __ldg(&Win[(size_t)k * G3 + tid]);
                    float w1 = __ldg(&Win[(size_t)k * G3 + UU + tid]);
                    float w2 = __ldg(&Win[(size_t)k * G3 + 2 * UU + tid]);
                    #pragma unroll
                    for (int r = 0; r < 8; ++r) {
                        float a = asr[r * DD + k];
                        a0[r] += a * w0; a1[r] += a * w1; a2[r] += a * w2;
                    }
                }
                #pragma unroll
                for (int r = 0; r < 8; ++r) {
                    size_t ro = (size_t)(rbase + rs * 8 + r) * G3;
                    g_xg[ro + tid]          = a0[r] + bz;
                    g_xg[ro + UU + tid]     = a1[r] + br;
                    g_xg[ro + 2 * UU + tid] = a2[r] + bhh;
                }
            }
        }
    }
    group_sync(gid);

    const float invT = 1.0f / (float)TT;

    // gate-input registers, prefetched one step ahead
    float xz = 0.f, xr = 0.f, xh = 0.f;
    if (tid < 128) {
        const int uq = tid & 7, bb2 = tid >> 3;
        const size_t xo = ((size_t)(b0 + bb2) * TT + 0) * G3 + u0 + uq;
        xz = __ldg(&g_xg[xo]);
        xr = __ldg(&g_xg[xo + UU]);
        xh = __ldg(&g_xg[xo + 2 * UU]);
    }

    for (int c0 = 0; c0 < TT; c0 += CH) {
        // ---------- chunk-base GEMM: 16 group batches x 2 j-halves ----------
        if (c0 > 0) {
            float* Hs = BIG;
            const int cb   = blk >> 1;
            const int jh   = blk & 1;
            const int kb   = c0 >> 1;
            const int jbeg = jh * kb;
            const float* hrow = out  + ((size_t)cb * TT + jbeg) * UU;
            const float* crow = cond + ((size_t)cb * TT + c0) * TT + jbeg;

            float acc[2][8];
            #pragma unroll
            for (int a = 0; a < 2; ++a)
                #pragma unroll
                for (int q = 0; q < 8; ++q) acc[a][q] = 0.f;

            const int lg = tid >> 5;
            const int ug = tid & 31;

            for (int jt = 0; jt < kb; jt += 32) {
                const int jn = (kb - jt < 32) ? (kb - jt) : 32;
                __syncthreads();
                for (int idx = tid; idx < jn * UU; idx += TPB)
                    Hs[idx] = __ldcg(&hrow[(size_t)jt * UU + idx]);
                {
                    int l = tid >> 5, jj = tid & 31;
                    if (jj < jn)
                        Cs[jj * CH + l] = __ldg(&crow[(size_t)l * TT + jt + jj]);
                }
                __syncthreads();
                if (tid < 128) {
                    for (int jj = 0; jj < jn; ++jj) {
                        float cv0 = Cs[jj * CH + lg];
                        float cv1 = Cs[jj * CH + lg + 4];
                        const float4* h4 = (const float4*)&Hs[jj * UU + ug * 8];
                        float4 ha = h4[0], hb2 = h4[1];
                        acc[0][0] += cv0 * ha.x;  acc[0][1] += cv0 * ha.y;
                        acc[0][2] += cv0 * ha.z;  acc[0][3] += cv0 * ha.w;
                        acc[0][4] += cv0 * hb2.x; acc[0][5] += cv0 * hb2.y;
                        acc[0][6] += cv0 * hb2.z; acc[0][7] += cv0 * hb2.w;
                        acc[1][0] += cv1 * ha.x;  acc[1][1] += cv1 * ha.y;
                        acc[1][2] += cv1 * ha.z;  acc[1][3] += cv1 * ha.w;
                        acc[1][4] += cv1 * hb2.x; acc[1][5] += cv1 * hb2.y;
                        acc[1][6] += cv1 * hb2.z; acc[1][7] += cv1 * hb2.w;
                    }
                }
            }
            if (tid < 128) {
                #pragma unroll
                for (int li = 0; li < 2; ++li) {
                    const int l = lg + li * 4;
                    float* dst = &g_basep[jh][cb][l][ug * 8];
                    ((float4*)dst)[0] = make_float4(acc[li][0], acc[li][1],
                                                    acc[li][2], acc[li][3]);
                    ((float4*)dst)[1] = make_float4(acc[li][4], acc[li][5],
                                                    acc[li][6], acc[li][7]);
                }
            }
            group_sync(gid);
        }

        // ---------------- sequential steps within chunk ----------------
        for (int l = 0; l < CH; ++l) {
            const int i = c0 + l;
            const int lnext = (l < CH - 1) ? (l + 1) : 0;
            float* CsmCur = Csm + (l & 1) * 128;
            float* CsmNxt = Csm + ((l + 1) & 1) * 128;

            // ---- phase A: correction + base -> Ab (128 u-pairs x 2 bb-halves) ----
            {
                const int u2  = tid & 127;
                const int bbh = tid >> 7;
                float2 acc[8];
                if (c0 > 0) {
                    #pragma unroll
                    for (int r = 0; r < 8; ++r) {
                        const int bb = bbh * 8 + r;
                        float2 p0 = __ldcg((const float2*)&g_basep[0][b0 + bb][l][2 * u2]);
                        float2 p1 = __ldcg((const float2*)&g_basep[1][b0 + bb][l][2 * u2]);
                        acc[r].x = p0.x + p1.x;
                        acc[r].y = p0.y + p1.y;
                    }
                } else {
                    #pragma unroll
                    for (int r = 0; r < 8; ++r) acc[r] = make_float2(0.f, 0.f);
                }
                for (int jj = 0; jj < l; ++jj) {
                    #pragma unroll
                    for (int r = 0; r < 8; ++r) {
                        const int bb = bbh * 8 + r;
                        float cv = CsmCur[jj * 16 + bb];
                        float2 h = __ldcg((const float2*)
                            &out[((size_t)(b0 + bb) * TT + c0 + jj) * UU + 2 * u2]);
                        acc[r].x += cv * h.x;
                        acc[r].y += cv * h.y;
                    }
                }
                // packed batch-pair writes: 4 x STS.128, conflict-free
                #pragma unroll
                for (int p = 0; p < 4; ++p) {
                    const int bpw = bbh * 4 + p;
                    ulonglong2 e;
                    e.x = pack2(acc[2 * p].x * invT, acc[2 * p + 1].x * invT);
                    e.y = pack2(acc[2 * p].y * invT, acc[2 * p + 1].y * invT);
                    ((ulonglong2*)Ab)[bpw * SAB + u2] = e;
                }
            }
            __syncthreads();

            // ---- prefetch next step's cond + gate inputs ----
            float cnext = 0.f, xzp = 0.f, xrp = 0.f, xhp = 0.f;
            if (tid < 128) {
                const int jj = tid >> 4, bb = tid & 15;
                if (jj < lnext)
                    cnext = __ldg(&cond[((size_t)(b0 + bb) * TT + (i + 1)) * TT
                                        + c0 + jj]);
                if (i + 1 < TT) {
                    const int uq = tid & 7, bb2 = tid >> 3;
                    const size_t xo = ((size_t)(b0 + bb2) * TT + (i + 1)) * G3 + u0 + uq;
                    xzp = __ldg(&g_xg[xo]);
                    xrp = __ldg(&g_xg[xo + UU]);
                    xhp = __ldg(&g_xg[xo + 2 * UU]);
                }
            }

            // ---- hg = next @ Wrec via packed FFMA2, col-grouped warps ----
            if (tid < 192) {
                const ulonglong2* wk = ((const ulonglong2*)Wk) + c;         // (k2,c)
                const ulonglong2* ab = ((const ulonglong2*)Ab) + bp * SAB;  // (bp,k2)
                ull acc0 = 0ull, acc1 = 0ull, acc2 = 0ull, acc3 = 0ull;
                #pragma unroll 8
                for (int k2 = 0; k2 < 128; k2 += 2) {
                    ulonglong2 w0 = wk[(size_t)k2 * 24];
                    ulonglong2 a0 = ab[k2];
                    ulonglong2 w1 = wk[(size_t)(k2 + 1) * 24];
                    ulonglong2 a1 = ab[k2 + 1];
                    FMA2(acc0, a0.x, w0.x);
                    FMA2(acc1, a0.y, w0.y);
                    FMA2(acc2, a1.x, w1.x);
                    FMA2(acc3, a1.y, w1.y);
                }
                ADD2(acc0, acc1);
                ADD2(acc2, acc3);
                ADD2(acc0, acc2);
                float g0, g1;
                unpack2(acc0, g0, g1);
                Gh[(2 * bp)     * 24 + c] = g0 + bh;
                Gh[(2 * bp + 1) * 24 + c] = g1 + bh;
            }
            __syncthreads();

            // ---- gates + output; stage next cond ----
            if (tid < 128) {
                const int uq = tid & 7, bb = tid >> 3;
                const int uu = u0 + uq;
                float hz = Gh[bb * 24 + uq];
                float hr = Gh[bb * 24 + 8 + uq];
                float hh = Gh[bb * 24 + 16 + uq];
                float z  = 1.0f / (1.0f + __expf(-(xz + hz)));
                float r  = 1.0f / (1.0f + __expf(-(xr + hr)));
                float hc = tanh_fast(xh + r * hh);
                float h  = ((const float*)Ab)[((bb >> 1) * SAB + (uu >> 1)) * 4
                                              + ((uu & 1) << 1) + (bb & 1)];
                out[((size_t)(b0 + bb) * TT + i) * UU + uu]
                    = z * h + (1.0f - z) * hc;
                if ((tid >> 4) < lnext) CsmNxt[tid] = cnext;
            }
            xz = xzp; xr = xrp; xh = xhp;
            group_sync(gid);
        }
    }
}

extern "C" void kernel_launch(void* const* d_in, const int* in_sizes, int n_in,
                              void* d_out, int out_size) {
    const float* x    = (const float*)d_in[0];
    const float* cond = (const float*)d_in[1];
    const float* Win  = (const float*)d_in[2];
    const float* Wrec = (const float*)d_in[3];
    const float* bias = (const float*)d_in[4];
    float* out = (float*)d_out;

    const int smem_bytes = SMEM_F * sizeof(float);
    static bool attr_set = false;
    if (!attr_set) {
        cudaFuncSetAttribute(dag_rnn_kernel,
                             cudaFuncAttributeMaxDynamicSharedMemorySize, smem_bytes);
        attr_set = true;
    }
    dag_rnn_kernel<<<NBLK, TPB, smem_bytes>>>(x, cond, Win, Wrec, bias, out);
}

// round 13
// speedup vs baseline: 1.2607x; 1.1646x over previous
#include <cuda_runtime.h>
#include <math.h>

typedef unsigned long long ull;

#define TT   512
#define BBAT 64
#define DD   128
#define UU   256
#define G3   768
#define NBLK 128
#define TPB  256
#define CH   8
#define NGRP 16
#define GBLK 8            // blocks per group (group = 4 batches, u split 8 ways)
#define WROW 260          // Wc row stride in floats (16B aligned, 4-cyc-floor LDS.128)
#define AROW 260          // Ab row stride in floats

// ---------------- device scratch ----------------
__device__ float g_xg[(size_t)BBAT * TT * G3];   // x @ W_in + bias0
__device__ float g_basep[2][BBAT][CH][UU];       // chunk-base partials (2 j-halves)
// per-group barrier state, 256B-strided
__device__ unsigned g_barcnt[NGRP * 64];
__device__ volatile unsigned g_bargen[NGRP * 64];

// packed f32x2 helpers (Blackwell; ptxas never emits FFMA2 from C++)
#define FMA2(acc, a, b) \
    asm("fma.rn.f32x2 %0, %1, %2, %0;" : "+l"(acc) : "l"(a), "l"(b))
#define ADD2(acc, a) \
    asm("add.rn.f32x2 %0, %1, %0;" : "+l"(acc) : "l"(a))
__device__ __forceinline__ void unpack2(ull v, float& x, float& y) {
    asm("mov.b64 {%0, %1}, %2;" : "=f"(x), "=f"(y) : "l"(v));
}
__device__ __forceinline__ float tanh_fast(float v) {
    float y; asm("tanh.approx.f32 %0, %1;" : "=f"(y) : "f"(v)); return y;
}

// Group barrier (R6-proven structure): 8 CTAs/group, all resident.
// Per-thread __threadfence (gpu-scope release) before arrival; central
// atomic count; single-leader nanosleep spin; fence on wake.
// Cross-block data is read via __ldcg (L2 = coherence point).
__device__ __forceinline__ void group_sync(int gid) {
    __threadfence();
    __syncthreads();
    if (threadIdx.x == 0) {
        const int sdx = gid * 64;
        unsigned g = g_bargen[sdx];
        if (atomicAdd(&g_barcnt[sdx], 1u) == GBLK - 1) {
            atomicExch(&g_barcnt[sdx], 0u);
            __threadfence();
            g_bargen[sdx] = g + 1;
        } else {
            while (g_bargen[sdx] == g) { __nanosleep(32); }
        }
        __threadfence();
    }
    __syncthreads();
}

// smem layout (float offsets)
#define WC_OFF   0        // Wc: 96 cols x 260 f (col-major, k contiguous) = 24960 f
#define AB_OFF   24960    // Ab: 4 batches x 260 f (next_state rows, k contiguous)
#define BIG_OFF  26000    // 8192 f union: stage0 As / chunk Hs
#define CS_OFF   34192    // 256 f chunk cond tile
#define CSM_OFF  34448    // 64 f per-step cond stage (double-buffered 2x32)
#define GH_OFF   34512    // 384 f h-side preactivations [4][96]
#define SMEM_F   34896    // 139584 B

__global__ void __launch_bounds__(TPB, 1) dag_rnn_kernel(
    const float* __restrict__ x,     // (B,T,D)
    const float* __restrict__ cond,  // (B,T,T)
    const float* __restrict__ Win,   // (D,3U)
    const float* __restrict__ Wrec,  // (U,3U)
    const float* __restrict__ bias,  // (2,3U)
    float* __restrict__ out)         // (B,T,U) == H storage
{
    extern __shared__ __align__(16) float smem[];
    float* Wc  = smem + WC_OFF;           // [cc][k], stride WROW
    float* Ab  = smem + AB_OFF;           // [bb][k], stride AROW
    float* BIG = smem + BIG_OFF;
    float* Cs  = smem + CS_OFF;
    float* Csm = smem + CSM_OFF;          // 2 x 32
    float* Gh  = smem + GH_OFF;           // [bb][cc]

    const int tid = threadIdx.x;
    const int blk = blockIdx.x;
    const int gid = blk >> 3;          // group (4 batches)
    const int s   = blk & 7;           // u-slice within group

    const int b0 = gid * 4;            // first batch of group
    const int us = 32 * s;             // u-slice origin

    // GEMM identity (tid<192): bq = batch-pair (0/1), cc = column 0..95
    const int cc = tid % 96;
    const int bq = tid / 96;
    const int gcol = (cc >> 5) * UU + us + (cc & 31);   // column in 3U gate space
    float bh = 0.f;
    if (tid < 192) bh = bias[G3 + gcol];

    // ---- preload Wrec slice col-major: Wc[cc*WROW + k] ----
    for (int idx = tid; idx < 96 * UU; idx += TPB) {
        int ccc = idx >> 8, k = idx & 255;
        int colc = (ccc >> 5) * UU + us + (ccc & 31);
        Wc[ccc * WROW + k] = Wrec[(size_t)k * G3 + colc];
    }

    // ================= stage 0: g_xg = x @ Win + bias0 =================
    // 8 group blocks x 256 rows = exactly the group's 4 batches (4*512 rows)
    {
        float* As = BIG;                       // 32 x 128
        const float bz  = bias[tid];
        const float br  = bias[UU + tid];
        const float bhh = bias[2 * UU + tid];
        const int row0 = blk * 256;
        for (int rt = 0; rt < 8; ++rt) {
            const int rbase = row0 + rt * 32;
            __syncthreads();
            for (int idx = tid; idx < 32 * DD; idx += TPB)
                As[idx] = x[(size_t)rbase * DD + idx];
            __syncthreads();
            for (int rs = 0; rs < 4; ++rs) {
                float a0[8], a1[8], a2[8];
                #pragma unroll
                for (int r = 0; r < 8; ++r) { a0[r] = 0.f; a1[r] = 0.f; a2[r] = 0.f; }
                const float* asr = As + (rs * 8) * DD;
                #pragma unroll 4
                for (int k = 0; k < DD; ++k) {
                    float w0 = __ldg(&Win[(size_t)k * G3 + tid]);
                    float w1 = __ldg(&Win[(size_t)k * G3 + UU + tid]);
                    float w2 = __ldg(&Win[(size_t)k * G3 + 2 * UU + tid]);
                    #pragma unroll
                    for (int r = 0; r < 8; ++r) {
                        float a = asr[r * DD + k];
                        a0[r] += a * w0; a1[r] += a * w1; a2[r] += a * w2;
                    }
                }
                #pragma unroll
                for (int r = 0; r < 8; ++r) {
                    size_t ro = (size_t)(rbase + rs * 8 + r) * G3;
                    g_xg[ro + tid]          = a0[r] + bz;
                    g_xg[ro + UU + tid]     = a1[r] + br;
                    g_xg[ro + 2 * UU + tid] = a2[r] + bhh;
                }
            }
        }
    }
    group_sync(gid);

    const float invT = 1.0f / (float)TT;

    // gate-input registers (tid<128: bb = tid>>5, uq = tid&31), one step ahead
    float xz = 0.f, xr = 0.f, xh = 0.f;
    if (tid < 128) {
        const int uq = tid & 31, bb2 = tid >> 5;
        const size_t xo = ((size_t)(b0 + bb2) * TT + 0) * G3 + us + uq;
        xz = __ldg(&g_xg[xo]);
        xr = __ldg(&g_xg[xo + UU]);
        xh = __ldg(&g_xg[xo + 2 * UU]);
    }

    for (int c0 = 0; c0 < TT; c0 += CH) {
        // ---------- chunk-base GEMM: 4 group batches x 2 j-halves ----------
        if (c0 > 0) {
            float* Hs = BIG;
            const int cb   = b0 + (s >> 1);    // batch for this block
            const int jh   = s & 1;            // j-half
            const int kb   = c0 >> 1;
            const int jbeg = jh * kb;
            const float* hrow = out  + ((size_t)cb * TT + jbeg) * UU;
            const float* crow = cond + ((size_t)cb * TT + c0) * TT + jbeg;

            float acc[2][8];
            #pragma unroll
            for (int a = 0; a < 2; ++a)
                #pragma unroll
                for (int q = 0; q < 8; ++q) acc[a][q] = 0.f;

            const int lg = tid >> 5;
            const int ug = tid & 31;

            for (int jt = 0; jt < kb; jt += 32) {
                const int jn = (kb - jt < 32) ? (kb - jt) : 32;
                __syncthreads();
                for (int idx = tid; idx < jn * UU; idx += TPB)
                    Hs[idx] = __ldcg(&hrow[(size_t)jt * UU + idx]);
                {
                    int l = tid >> 5, jj = tid & 31;
                    if (jj < jn)
                        Cs[jj * CH + l] = __ldg(&crow[(size_t)l * TT + jt + jj]);
                }
                __syncthreads();
                if (tid < 128) {
                    for (int jj = 0; jj < jn; ++jj) {
                        float cv0 = Cs[jj * CH + lg];
                        float cv1 = Cs[jj * CH + lg + 4];
                        const float4* h4 = (const float4*)&Hs[jj * UU + ug * 8];
                        float4 ha = h4[0], hb2 = h4[1];
                        acc[0][0] += cv0 * ha.x;  acc[0][1] += cv0 * ha.y;
                        acc[0][2] += cv0 * ha.z;  acc[0][3] += cv0 * ha.w;
                        acc[0][4] += cv0 * hb2.x; acc[0][5] += cv0 * hb2.y;
                        acc[0][6] += cv0 * hb2.z; acc[0][7] += cv0 * hb2.w;
                        acc[1][0] += cv1 * ha.x;  acc[1][1] += cv1 * ha.y;
                        acc[1][2] += cv1 * ha.z;  acc[1][3] += cv1 * ha.w;
                        acc[1][4] += cv1 * hb2.x; acc[1][5] += cv1 * hb2.y;
                        acc[1][6] += cv1 * hb2.z; acc[1][7] += cv1 * hb2.w;
                    }
                }
            }
            if (tid < 128) {
                #pragma unroll
                for (int li = 0; li < 2; ++li) {
                    const int l = lg + li * 4;
                    float* dst = &g_basep[jh][cb][l][ug * 8];
                    ((float4*)dst)[0] = make_float4(acc[li][0], acc[li][1],
                                                    acc[li][2], acc[li][3]);
                    ((float4*)dst)[1] = make_float4(acc[li][4], acc[li][5],
                                                    acc[li][6], acc[li][7]);
                }
            }
            group_sync(gid);
        }

        // ---------------- sequential steps within chunk ----------------
        for (int l = 0; l < CH; ++l) {
            const int i = c0 + l;
            const int lnext = (l < CH - 1) ? (l + 1) : 0;
            float* CsmCur = Csm + (l & 1) * 32;
            float* CsmNxt = Csm + ((l + 1) & 1) * 32;

            // ---- phase A: full next_state for 4 batches (thread = u) ----
            {
                const int u = tid;             // 0..255
                float acc[4];
                if (c0 > 0) {
                    #pragma unroll
                    for (int bb = 0; bb < 4; ++bb)
                        acc[bb] = __ldcg(&g_basep[0][b0 + bb][l][u])
                                + __ldcg(&g_basep[1][b0 + bb][l][u]);
                } else {
                    #pragma unroll
                    for (int bb = 0; bb < 4; ++bb) acc[bb] = 0.f;
                }
                for (int jj = 0; jj < l; ++jj) {
                    #pragma unroll
                    for (int bb = 0; bb < 4; ++bb) {
                        float cv = CsmCur[jj * 4 + bb];
                        acc[bb] += cv * __ldcg(
                            &out[((size_t)(b0 + bb) * TT + c0 + jj) * UU + u]);
                    }
                }
                #pragma unroll
                for (int bb = 0; bb < 4; ++bb)
                    Ab[bb * AROW + u] = acc[bb] * invT;
            }
            __syncthreads();

            // ---- prefetch next step's cond + gate inputs ----
            float cnext = 0.f, xzp = 0.f, xrp = 0.f, xhp = 0.f;
            if (tid < 128) {
                const int jj = tid >> 2, bb = tid & 3;
                if (jj < lnext)
                    cnext = __ldg(&cond[((size_t)(b0 + bb) * TT + (i + 1)) * TT
                                        + c0 + jj]);
                if (i + 1 < TT) {
                    const int uq = tid & 31, bb2 = tid >> 5;
                    const size_t xo = ((size_t)(b0 + bb2) * TT + (i + 1)) * G3 + us + uq;
                    xzp = __ldg(&g_xg[xo]);
                    xrp = __ldg(&g_xg[xo + UU]);
                    xhp = __ldg(&g_xg[xo + 2 * UU]);
                }
            }

            // ---- hg = next @ Wrec via k-paired FFMA2 (192 threads) ----
            if (tid < 192) {
                const ulonglong2* wrow = (const ulonglong2*)Wc + cc * (WROW / 4);
                const ulonglong2* a0r  = (const ulonglong2*)Ab + (2 * bq)     * (AROW / 4);
                const ulonglong2* a1r  = (const ulonglong2*)Ab + (2 * bq + 1) * (AROW / 4);
                ull acc00 = 0ull, acc01 = 0ull, acc10 = 0ull, acc11 = 0ull;
                #pragma unroll 8
                for (int m2 = 0; m2 < 64; ++m2) {
                    ulonglong2 w  = wrow[m2];
                    ulonglong2 a0 = a0r[m2];
                    ulonglong2 a1 = a1r[m2];
                    FMA2(acc00, a0.x, w.x);
                    FMA2(acc01, a0.y, w.y);
                    FMA2(acc10, a1.x, w.x);
                    FMA2(acc11, a1.y, w.y);
                }
                ADD2(acc00, acc01);
                ADD2(acc10, acc11);
                float p0, p1, q0, q1;
                unpack2(acc00, p0, p1);
                unpack2(acc10, q0, q1);
                Gh[(2 * bq)     * 96 + cc] = (p0 + p1) + bh;
                Gh[(2 * bq + 1) * 96 + cc] = (q0 + q1) + bh;
            }
            __syncthreads();

            // ---- gates + output (4b x 32u = 128 threads); stage next cond ----
            if (tid < 128) {
                const int uq = tid & 31, bb = tid >> 5;
                float hz = Gh[bb * 96 + uq];
                float hr = Gh[bb * 96 + 32 + uq];
                float hh = Gh[bb * 96 + 64 + uq];
                float z  = 1.0f / (1.0f + __expf(-(xz + hz)));
                float r  = 1.0f / (1.0f + __expf(-(xr + hr)));
                float hc = tanh_fast(xh + r * hh);
                float h  = Ab[bb * AROW + us + uq];   // next_state
                out[((size_t)(b0 + bb) * TT + i) * UU + us + uq]
                    = z * h + (1.0f - z) * hc;
                if ((tid >> 2) < lnext) CsmNxt[tid] = cnext;
            }
            xz = xzp; xr = xrp; xh = xhp;
            group_sync(gid);
        }
    }
}

extern "C" void kernel_launch(void* const* d_in, const int* in_sizes, int n_in,
                              void* d_out, int out_size) {
    const float* x    = (const float*)d_in[0];
    const float* cond = (const float*)d_in[1];
    const float* Win  = (const float*)d_in[2];
    const float* Wrec = (const float*)d_in[3];
    const float* bias = (const float*)d_in[4];
    float* out = (float*)d_out;

    const int smem_bytes = SMEM_F * sizeof(float);
    static bool attr_set = false;
    if (!attr_set) {
        cudaFuncSetAttribute(dag_rnn_kernel,
                             cudaFuncAttributeMaxDynamicSharedMemorySize, smem_bytes);
        attr_set = true;
    }
    dag_rnn_kernel<<<NBLK, TPB, smem_bytes>>>(x, cond, Win, Wrec, bias, out);
}